// round 2
// baseline (speedup 1.0000x reference)
#include <cuda_runtime.h>

// ChamferDistance_755914244601: B=4, N=M=8192, 3D points.
// Fused single-pass kernel: each block computes a 128x256 tile of the distance
// matrix ONCE, updating row mins (d1) and col mins (d2) simultaneously.
// Inner math is packed f32x2 (FFMA2/FADD2): 4 lane-inst per pair total.

#define BB 4
#define NN 8192
#define MM 8192
#define TPB 256
#define BR  128   // rows per block (xyz1 points)
#define BC  256   // cols per block (xyz2 points)
#define KR  8     // rows per thread  (ty: 16 groups)
#define KC  16    // cols per thread  (tx: 16 groups)
#define NCP (KC/2)

typedef unsigned long long ull;

// Global min accumulators (order-preserving uint keys of float values)
__device__ unsigned int g_rmin[BB * NN];
__device__ unsigned int g_cmin[BB * MM];

static __device__ __forceinline__ ull pk2(float lo, float hi) {
    ull r; asm("mov.b64 %0, {%1, %2};" : "=l"(r) : "f"(lo), "f"(hi)); return r;
}
static __device__ __forceinline__ void upk2(ull v, float& lo, float& hi) {
    asm("mov.b64 {%0, %1}, %2;" : "=f"(lo), "=f"(hi) : "l"(v));
}
static __device__ __forceinline__ ull ffma2(ull a, ull b, ull c) {
    ull d; asm("fma.rn.f32x2 %0, %1, %2, %3;" : "=l"(d) : "l"(a), "l"(b), "l"(c)); return d;
}
static __device__ __forceinline__ ull fadd2(ull a, ull b) {
    ull d; asm("add.rn.f32x2 %0, %1, %2;" : "=l"(d) : "l"(a), "l"(b)); return d;
}

// Order-preserving float -> uint key (handles negatives), and inverse.
static __device__ __forceinline__ unsigned int okey(float f) {
    unsigned int b = __float_as_uint(f);
    return (b & 0x80000000u) ? ~b : (b | 0x80000000u);
}
static __device__ __forceinline__ float odec(unsigned int k) {
    return __uint_as_float((k & 0x80000000u) ? (k ^ 0x80000000u) : ~k);
}

__global__ void init_kernel() {
    int i = blockIdx.x * blockDim.x + threadIdx.x;
    if (i < BB * NN) g_rmin[i] = 0xFFFFFFFFu;
    if (i < BB * MM) g_cmin[i] = 0xFFFFFFFFu;
}

__global__ void __launch_bounds__(TPB, 2)
chamfer_tile(const float* __restrict__ x1, const float* __restrict__ x2)
{
    __shared__ float rowraw[BR * 3];
    __shared__ float colraw[BC * 3];
    __shared__ float4 RA[BR], RB[BR];          // rows packed: (x,x,y,y) / (z,z,s1,s1)
    __shared__ float4 CA[BC / 2], CB[BC / 2];  // colpairs: (-2xa,-2xb,-2ya,-2yb) / (-2za,-2zb,s2a,s2b)
    __shared__ unsigned int rmin_s[BR];
    __shared__ unsigned int cmin_s[BC];

    const int tid = threadIdx.x;
    const int tx = tid & 15;
    const int ty = tid >> 4;
    const int b = blockIdx.z;
    const int rowbase = blockIdx.y * BR;
    const int colbase = blockIdx.x * BC;

    // Stage raw points coalesced.
    const float* r0 = x1 + ((size_t)b * NN + rowbase) * 3;
    const float* c0 = x2 + ((size_t)b * MM + colbase) * 3;
    for (int i = tid; i < BR * 3; i += TPB) rowraw[i] = r0[i];
    for (int i = tid; i < BC * 3; i += TPB) colraw[i] = c0[i];
    if (tid < BR) rmin_s[tid] = 0xFFFFFFFFu;
    cmin_s[tid] = 0xFFFFFFFFu;
    __syncthreads();

    // Pack tiles for f32x2 consumption.
    if (tid < BR) {
        float x = rowraw[tid * 3], y = rowraw[tid * 3 + 1], z = rowraw[tid * 3 + 2];
        float s = x * x + y * y + z * z;
        RA[tid] = make_float4(x, x, y, y);
        RB[tid] = make_float4(z, z, s, s);
    }
    {
        float x = colraw[tid * 3], y = colraw[tid * 3 + 1], z = colraw[tid * 3 + 2];
        float w = x * x + y * y + z * z;
        float* ca = (float*)CA;
        float* cb = (float*)CB;
        int p = tid >> 1, e = tid & 1;
        ca[p * 4 + e]     = -2.0f * x;
        ca[p * 4 + 2 + e] = -2.0f * y;
        cb[p * 4 + e]     = -2.0f * z;
        cb[p * 4 + 2 + e] = w;
    }
    __syncthreads();

    // Thread's private column cache: 8 colpairs = 16 fixed columns, in registers.
    ull cxx[NCP], cyy[NCP], czz[NCP], cww[NCP];
#pragma unroll
    for (int cp = 0; cp < NCP; cp++) {
        int p = tx * NCP + cp;
        ulonglong2 a  = ((const ulonglong2*)CA)[p];
        ulonglong2 bb = ((const ulonglong2*)CB)[p];
        cxx[cp] = a.x; cyy[cp] = a.y; czz[cp] = bb.x; cww[cp] = bb.y;
    }

    float colacc[KC];
#pragma unroll
    for (int j = 0; j < KC; j++) colacc[j] = 3.4e38f;

#pragma unroll
    for (int k = 0; k < KR; k++) {
        const int r = ty * KR + k;
        ulonglong2 pa = ((const ulonglong2*)RA)[r];
        ulonglong2 pb = ((const ulonglong2*)RB)[r];
        const ull rx = pa.x, ry = pa.y, rz = pb.x, rs = pb.y;
        float racc0 = 3.4e38f, racc1 = 3.4e38f;
#pragma unroll
        for (int cp = 0; cp < NCP; cp++) {
            // v = sq2_j - 2*dot   (row candidate; sq2 folded into the chain)
            ull v = ffma2(cxx[cp], rx, ffma2(cyy[cp], ry, ffma2(czz[cp], rz, cww[cp])));
            float vl, vh; upk2(v, vl, vh);
            racc0 = fminf(racc0, vl);
            racc1 = fminf(racc1, vh);
            // c = v + sq1_i = full squared distance (col candidate)
            ull c = fadd2(v, rs);
            float cl, ch; upk2(c, cl, ch);
            colacc[2 * cp]     = fminf(colacc[2 * cp], cl);
            colacc[2 * cp + 1] = fminf(colacc[2 * cp + 1], ch);
        }
        atomicMin(&rmin_s[r], okey(fminf(racc0, racc1)));
    }
#pragma unroll
    for (int j = 0; j < KC; j++)
        atomicMin(&cmin_s[tx * KC + j], okey(colacc[j]));
    __syncthreads();

    if (tid < BR) atomicMin(&g_rmin[(size_t)b * NN + rowbase + tid], rmin_s[tid]);
    atomicMin(&g_cmin[(size_t)b * MM + colbase + tid], cmin_s[tid]);
}

// out[0 .. B*N)  = d1 = rowmin + sq1   (sq1 recomputed here, it was folded out)
// out[B*N .. +B*M) = d2 = colmin (already full distance)
__global__ void final_kernel(const float* __restrict__ x1, float* __restrict__ out)
{
    int i = blockIdx.x * blockDim.x + threadIdx.x;
    if (i < BB * NN) {
        const float* p = x1 + (size_t)i * 3;
        float s = p[0] * p[0] + p[1] * p[1] + p[2] * p[2];
        out[i] = odec(g_rmin[i]) + s;
    } else if (i < BB * NN + BB * MM) {
        out[i] = odec(g_cmin[i - BB * NN]);
    }
}

extern "C" void kernel_launch(void* const* d_in, const int* in_sizes, int n_in,
                              void* d_out, int out_size)
{
    const float* xyz1 = (const float*)d_in[0];   // [B, N, 3]
    const float* xyz2 = (const float*)d_in[1];   // [B, M, 3]
    float* out = (float*)d_out;

    int mx = (BB * NN > BB * MM) ? BB * NN : BB * MM;
    init_kernel<<<(mx + TPB - 1) / TPB, TPB>>>();

    dim3 grid(MM / BC, NN / BR, BB);   // (32, 64, 4) = 8192 blocks
    chamfer_tile<<<grid, TPB>>>(xyz1, xyz2);

    const int total = BB * NN + BB * MM;
    final_kernel<<<(total + TPB - 1) / TPB, TPB>>>(xyz1, out);
}

// round 4
// speedup vs baseline: 3.0400x; 3.0400x over previous
#include <cuda_runtime.h>

// ChamferDistance_755914244601: B=4, N=M=8192, 3D points.
// Fused: each block computes a 256-col x 4096-row stripe of the distance
// matrix once, accumulating col mins in registers and row mins via one
// STS/row + deferred chunk reduction. Inner math packed f32x2.

#define BB 4
#define NN 8192
#define MM 8192
#define BC 256          // cols per block
#define KC 8            // cols per lane
#define NCP (KC / 2)    // colpairs per lane
#define TPB 256
#define NWARP 8
#define CH 128          // rows per chunk
#define RPW (CH / NWARP)
#define ROWSPLIT 2
#define NROWS (NN / ROWSPLIT)
#define NCHUNK (NROWS / CH)
#define NCB (MM / BC)   // 32 col blocks

typedef unsigned long long ull;

__device__ float g_rowpart[BB * NCB * NN];      // [b][colblock][row]
__device__ float g_colpart[BB * ROWSPLIT * MM]; // [b][split][col]

static __device__ __forceinline__ ull pk2(float lo, float hi) {
    ull r; asm("mov.b64 %0, {%1, %2};" : "=l"(r) : "f"(lo), "f"(hi)); return r;
}
static __device__ __forceinline__ void upk2(ull v, float& lo, float& hi) {
    asm("mov.b64 {%0, %1}, %2;" : "=f"(lo), "=f"(hi) : "l"(v));
}
static __device__ __forceinline__ ull ffma2(ull a, ull b, ull c) {
    ull d; asm("fma.rn.f32x2 %0, %1, %2, %3;" : "=l"(d) : "l"(a), "l"(b), "l"(c)); return d;
}
static __device__ __forceinline__ ull fadd2(ull a, ull b) {
    ull d; asm("add.rn.f32x2 %0, %1, %2;" : "=l"(d) : "l"(a), "l"(b)); return d;
}

__global__ void __launch_bounds__(TPB, 2)
chamfer_fused(const float* __restrict__ x1, const float* __restrict__ x2)
{
    __shared__ ulonglong2 RA[CH];     // (x,x),(y,y) per row
    __shared__ ulonglong2 RB[CH];     // (z,z),(s1,s1) per row
    __shared__ float4 colsm[BC];      // (-2x,-2y,-2z,s2) per col
    __shared__ float cand[CH][33];    // row-min candidates, padded stride

    const int tid  = threadIdx.x;
    const int lane = tid & 31;
    const int w    = tid >> 5;
    const int b     = blockIdx.z;
    const int split = blockIdx.y;
    const int colbase  = blockIdx.x * BC;
    const int rowbase0 = split * NROWS;

    // ---- prologue: load + preprocess the 256-col tile ----
    if (tid < BC) {
        const float* p = x2 + ((size_t)b * MM + colbase + tid) * 3;
        float x = p[0], y = p[1], z = p[2];
        colsm[tid] = make_float4(-2.0f * x, -2.0f * y, -2.0f * z,
                                 x * x + y * y + z * z);
    }
    __syncthreads();

    // Each lane caches its 4 colpairs in registers (every warp duplicates).
    ull cxx[NCP], cyy[NCP], czz[NCP], cww[NCP];
#pragma unroll
    for (int cp = 0; cp < NCP; cp++) {
        float4 a = colsm[lane * KC + 2 * cp];
        float4 c = colsm[lane * KC + 2 * cp + 1];
        cxx[cp] = pk2(a.x, c.x);
        cyy[cp] = pk2(a.y, c.y);
        czz[cp] = pk2(a.z, c.z);
        cww[cp] = pk2(a.w, c.w);
    }

    float colacc[KC];
#pragma unroll
    for (int j = 0; j < KC; j++) colacc[j] = 3.4e38f;

    // ---- main loop: stream 4096 rows in 128-row chunks ----
    for (int ch = 0; ch < NCHUNK; ch++) {
        const int rowbase = rowbase0 + ch * CH;

        __syncthreads();   // cand/RA/RB readers of previous chunk are done
        if (tid < CH) {
            const float* p = x1 + ((size_t)b * NN + rowbase + tid) * 3;
            float x = p[0], y = p[1], z = p[2];
            float s = x * x + y * y + z * z;
            RA[tid] = make_ulonglong2(pk2(x, x), pk2(y, y));
            RB[tid] = make_ulonglong2(pk2(z, z), pk2(s, s));
        }
        __syncthreads();

        // warp w handles rows [w*16, w*16+16) of this chunk
#pragma unroll
        for (int rr = 0; rr < RPW; rr++) {
            const int r = w * RPW + rr;
            const ulonglong2 ra = RA[r];   // LDS.128 broadcast
            const ulonglong2 rb = RB[r];
            float racc0 = 3.4e38f, racc1 = 3.4e38f;
#pragma unroll
            for (int cp = 0; cp < NCP; cp++) {
                // v = s2_j - 2*dot(i,j)    (row candidate, s1 folded out)
                ull v = ffma2(cxx[cp], ra.x,
                        ffma2(cyy[cp], ra.y,
                        ffma2(czz[cp], rb.x, cww[cp])));
                float vl, vh; upk2(v, vl, vh);
                racc0 = fminf(racc0, vl);
                racc1 = fminf(racc1, vh);
                // c = v + s1_i = full squared distance (col candidate)
                ull c = fadd2(v, rb.y);
                float cl, chh; upk2(c, cl, chh);
                colacc[2 * cp]     = fminf(colacc[2 * cp], cl);
                colacc[2 * cp + 1] = fminf(colacc[2 * cp + 1], chh);
            }
            cand[r][lane] = fminf(racc0, racc1);
        }
        __syncthreads();

        // chunk row-reduce: 2 threads per row, conflict-free by stride-33 pad
        {
            const int r = tid >> 1;
            const int h = tid & 1;
            float m = cand[r][h * 16 + 0];
#pragma unroll
            for (int i = 1; i < 16; i++)
                m = fminf(m, cand[r][h * 16 + i]);
            m = fminf(m, __shfl_xor_sync(0xFFFFFFFFu, m, 1));
            if (h == 0)
                g_rowpart[((size_t)b * NCB + blockIdx.x) * NN + rowbase + r] = m;
        }
    }

    // ---- epilogue: reduce colacc across the 8 warps (reuse cand as scratch) ----
    float* colred = &cand[0][0];   // needs 8*256 floats <= 128*33
    __syncthreads();
#pragma unroll
    for (int j = 0; j < KC; j++)
        colred[w * BC + lane * KC + j] = colacc[j];
    __syncthreads();
    {
        float m = colred[tid];
#pragma unroll
        for (int ww = 1; ww < NWARP; ww++)
            m = fminf(m, colred[ww * BC + tid]);
        g_colpart[((size_t)b * ROWSPLIT + split) * MM + colbase + tid] = m;
    }
}

// out[0..B*N) = d1 = min over colblocks of rowpart + s1
// out[B*N..)  = d2 = min over splits of colpart
__global__ void final_kernel(const float* __restrict__ x1, float* __restrict__ out)
{
    const int i = blockIdx.x * blockDim.x + threadIdx.x;
    if (i < BB * NN) {
        const int b = i / NN, row = i % NN;
        float m = 3.4e38f;
#pragma unroll
        for (int cb = 0; cb < NCB; cb++)
            m = fminf(m, g_rowpart[((size_t)b * NCB + cb) * NN + row]);
        const float* p = x1 + (size_t)i * 3;
        out[i] = m + p[0] * p[0] + p[1] * p[1] + p[2] * p[2];
    } else if (i < BB * NN + BB * MM) {
        const int j = i - BB * NN;
        const int b = j / MM, col = j % MM;
        float m = fminf(g_colpart[((size_t)b * ROWSPLIT + 0) * MM + col],
                        g_colpart[((size_t)b * ROWSPLIT + 1) * MM + col]);
        out[i] = m;
    }
}

extern "C" void kernel_launch(void* const* d_in, const int* in_sizes, int n_in,
                              void* d_out, int out_size)
{
    const float* xyz1 = (const float*)d_in[0];   // [B, N, 3]
    const float* xyz2 = (const float*)d_in[1];   // [B, M, 3]
    float* out = (float*)d_out;

    dim3 grid(NCB, ROWSPLIT, BB);   // (32, 2, 4) = 256 blocks
    chamfer_fused<<<grid, TPB>>>(xyz1, xyz2);

    const int total = BB * NN + BB * MM;
    final_kernel<<<(total + TPB - 1) / TPB, TPB>>>(xyz1, out);
}